// round 2
// baseline (speedup 1.0000x reference)
#include <cuda_runtime.h>

// HierarchicalRouter: two-level MoE router.
//   x               [16384, 2048] f32
//   group_gate_w    [8, 2048]     f32
//   expert_gate_w   [64, 2048]    f32
// out = concat(valid_mask[16384,64] as f32 0/1, normalized_weights[16384,64])
//
// R2: fused GEMM (M=16384, N=72, K=2048) with packed fp32x2 FFMA.
// Key change vs R1: weights are stored PRE-DUPLICATED in smem ((w,w) pairs,
// two splat-pairs per 16B), so the inner loop has zero MOV-splats:
// per k per thread = 1 LDS.128 (4 tokens) + 4 LDS.128 + 1 LDS.64 (9 expert
// splats) + 18 FFMA2.

#define N_TOKENS 16384
#define DIM      2048
#define BM       128
#define BK       16
#define NITER    (DIM / BK)
#define THREADS  256
#define WSTRIDE  73     // logits stride (epilogue)
#define WGPAD    24     // floats per warp's dup-weight region (9 pairs + pad, 96B)
#define WROW     (8 * WGPAD)   // 192 floats per k row

__device__ __forceinline__ void ffma2(unsigned long long& acc,
                                      unsigned long long a,
                                      unsigned long long b) {
    asm("fma.rn.f32x2 %0, %1, %2, %0;" : "+l"(acc) : "l"(a), "l"(b));
}

struct SmemTiles {
    float xs[2][BK][BM];     // transposed x tile: [buf][k][token]   (16 KB)
    float wd[2][BK][WROW];   // duplicated weights: [buf][k][...]    (24 KB)
};

__global__ __launch_bounds__(THREADS, 1)
void router_kernel(const float* __restrict__ x,
                   const float* __restrict__ ggw,
                   const float* __restrict__ egw,
                   float* __restrict__ out)
{
    __shared__ union {
        SmemTiles t;
        float logits[BM * WSTRIDE];  // reused after mainloop
    } sm;

    const int tid  = threadIdx.x;
    const int tg   = tid & 31;        // token group: tokens 4*tg .. 4*tg+3
    const int egp  = tid >> 5;        // expert group 0..7 (one per warp)
    const int e0   = egp * 9;         // experts e0..e0+8
    const int tok0 = blockIdx.x * BM;

    // ---- gmem loader mapping ----
    // x: thread (ltok, lhalf) loads float4 at k-quads {lhalf, 2+lhalf}
    const int ltok  = tid >> 1;
    const int lhalf = tid & 1;
    const float* xrow = x + (size_t)(tok0 + ltok) * DIM;

    // w: i in [0,288): e = i>>2, q = i&3; thread does i=tid (+256 if tid<32)
    const int we0 = tid >> 2;           // 0..63
    const int wq0 = tid & 3;
    const float* wrow0 = (we0 < 8) ? (ggw + (size_t)we0 * DIM)
                                   : (egw + (size_t)(we0 - 8) * DIM);
    const int wd0 = (we0 / 9) * WGPAD + (we0 % 9) * 2;  // dup-pair float offset
    const int we1 = (tid + 256) >> 2;   // 64..71 (tid<32 only)
    const int wq1 = (tid + 256) & 3;
    const float* wrow1 = egw + (size_t)(we1 - 8) * DIM;
    const int wd1 = (we1 / 9) * WGPAD + (we1 % 9) * 2;

    unsigned long long acc[2][9];
#pragma unroll
    for (int p = 0; p < 2; p++)
#pragma unroll
        for (int j = 0; j < 9; j++) acc[p][j] = 0ull;

    float4 xa, xb, wa, wb;

    auto ldg_tile = [&](int it) {
        const int k0 = it * BK;
        xa = *reinterpret_cast<const float4*>(xrow + k0 + lhalf * 4);
        xb = *reinterpret_cast<const float4*>(xrow + k0 + (2 + lhalf) * 4);
        wa = *reinterpret_cast<const float4*>(wrow0 + k0 + wq0 * 4);
        if (tid < 32)
            wb = *reinterpret_cast<const float4*>(wrow1 + k0 + wq1 * 4);
    };

    auto sts_tile = [&](int b) {
        // x transpose
        sm.t.xs[b][lhalf * 4 + 0][ltok] = xa.x;
        sm.t.xs[b][lhalf * 4 + 1][ltok] = xa.y;
        sm.t.xs[b][lhalf * 4 + 2][ltok] = xa.z;
        sm.t.xs[b][lhalf * 4 + 3][ltok] = xa.w;
        sm.t.xs[b][(2 + lhalf) * 4 + 0][ltok] = xb.x;
        sm.t.xs[b][(2 + lhalf) * 4 + 1][ltok] = xb.y;
        sm.t.xs[b][(2 + lhalf) * 4 + 2][ltok] = xb.z;
        sm.t.xs[b][(2 + lhalf) * 4 + 3][ltok] = xb.w;
        // duplicated weight stores: (v, v) per value
        {
            const float v[4] = {wa.x, wa.y, wa.z, wa.w};
#pragma unroll
            for (int i = 0; i < 4; i++) {
                float2* p = reinterpret_cast<float2*>(
                    &sm.t.wd[b][wq0 * 4 + i][wd0]);
                *p = make_float2(v[i], v[i]);
            }
        }
        if (tid < 32) {
            const float v[4] = {wb.x, wb.y, wb.z, wb.w};
#pragma unroll
            for (int i = 0; i < 4; i++) {
                float2* p = reinterpret_cast<float2*>(
                    &sm.t.wd[b][wq1 * 4 + i][wd1]);
                *p = make_float2(v[i], v[i]);
            }
        }
    };

    const int wbase = egp * WGPAD;

    auto compute = [&](int b) {
#pragma unroll
        for (int k = 0; k < BK; k++) {
            // 4 tokens as two packed pairs: one LDS.128
            ulonglong2 xp = *reinterpret_cast<const ulonglong2*>(
                &sm.t.xs[b][k][tg * 4]);
            // 9 expert splat-pairs: 4x LDS.128 + 1x LDS.64 (warp-broadcast)
            const float* wr = &sm.t.wd[b][k][wbase];
            ulonglong2 w01 = *reinterpret_cast<const ulonglong2*>(wr + 0);
            ulonglong2 w23 = *reinterpret_cast<const ulonglong2*>(wr + 4);
            ulonglong2 w45 = *reinterpret_cast<const ulonglong2*>(wr + 8);
            ulonglong2 w67 = *reinterpret_cast<const ulonglong2*>(wr + 12);
            unsigned long long w8 =
                *reinterpret_cast<const unsigned long long*>(wr + 16);

            ffma2(acc[0][0], xp.x, w01.x); ffma2(acc[1][0], xp.y, w01.x);
            ffma2(acc[0][1], xp.x, w01.y); ffma2(acc[1][1], xp.y, w01.y);
            ffma2(acc[0][2], xp.x, w23.x); ffma2(acc[1][2], xp.y, w23.x);
            ffma2(acc[0][3], xp.x, w23.y); ffma2(acc[1][3], xp.y, w23.y);
            ffma2(acc[0][4], xp.x, w45.x); ffma2(acc[1][4], xp.y, w45.x);
            ffma2(acc[0][5], xp.x, w45.y); ffma2(acc[1][5], xp.y, w45.y);
            ffma2(acc[0][6], xp.x, w67.x); ffma2(acc[1][6], xp.y, w67.x);
            ffma2(acc[0][7], xp.x, w67.y); ffma2(acc[1][7], xp.y, w67.y);
            ffma2(acc[0][8], xp.x, w8);    ffma2(acc[1][8], xp.y, w8);
        }
    };

    // ---- mainloop: double-buffered ----
    ldg_tile(0);
    sts_tile(0);
    __syncthreads();
    int cur = 0;
    for (int it = 0; it < NITER; ++it) {
        if (it + 1 < NITER) ldg_tile(it + 1);
        compute(cur);
        if (it + 1 < NITER) sts_tile(cur ^ 1);
        __syncthreads();
        cur ^= 1;
    }

    // ---- stage logits to smem: [token][expert], stride WSTRIDE ----
#pragma unroll
    for (int j = 0; j < 9; j++) {
        float2 p0 = *reinterpret_cast<float2*>(&acc[0][j]);
        float2 p1 = *reinterpret_cast<float2*>(&acc[1][j]);
        const int e = e0 + j;
        sm.logits[(tg * 4 + 0) * WSTRIDE + e] = p0.x;
        sm.logits[(tg * 4 + 1) * WSTRIDE + e] = p0.y;
        sm.logits[(tg * 4 + 2) * WSTRIDE + e] = p1.x;
        sm.logits[(tg * 4 + 3) * WSTRIDE + e] = p1.y;
    }
    __syncthreads();

    // ---- epilogue: one thread per token ----
    if (tid < BM) {
        float* L = &sm.logits[tid * WSTRIDE];  // [0..7] group, [8..71] expert

        // group softmax
        float gl[8];
#pragma unroll
        for (int g = 0; g < 8; g++) gl[g] = L[g];
        float gmax = gl[0];
#pragma unroll
        for (int g = 1; g < 8; g++) gmax = fmaxf(gmax, gl[g]);
        float ge[8], gsum = 0.0f;
#pragma unroll
        for (int g = 0; g < 8; g++) { ge[g] = expf(gl[g] - gmax); gsum += ge[g]; }
        float gp[8];
#pragma unroll
        for (int g = 0; g < 8; g++) gp[g] = ge[g] / gsum;

        unsigned long long vmask = 0ull;
        float swsum = 0.0f;
#pragma unroll
        for (int g = 0; g < 8; g++) {
            const bool gm = (gp[g] >= 0.125f);
            float el[8];
#pragma unroll
            for (int e = 0; e < 8; e++) el[e] = L[8 + g * 8 + e];
            float emax = el[0];
#pragma unroll
            for (int e = 1; e < 8; e++) emax = fmaxf(emax, el[e]);
            float ee[8], esum = 0.0f;
#pragma unroll
            for (int e = 0; e < 8; e++) { ee[e] = expf(el[e] - emax); esum += ee[e]; }
#pragma unroll
            for (int e = 0; e < 8; e++) {
                const float ep = ee[e] / esum;
                const bool val = gm && (ep >= 0.125f);
                const float sw = val ? gp[g] * ep : 0.0f;
                swsum += sw;
                L[8 + g * 8 + e] = sw;  // overwrite logit with selected weight
                if (val) vmask |= (1ull << (g * 8 + e));
            }
        }
        swsum = fmaxf(swsum, 1e-9f);
        const float inv = 1.0f / swsum;

        const int gt = tok0 + tid;
        float* om = out + (size_t)gt * 64;
        float* ow = out + (size_t)N_TOKENS * 64 + (size_t)gt * 64;
#pragma unroll
        for (int i = 0; i < 64; i += 4) {
            float4 m4, w4;
            m4.x = ((vmask >> (i + 0)) & 1ull) ? 1.0f : 0.0f;
            m4.y = ((vmask >> (i + 1)) & 1ull) ? 1.0f : 0.0f;
            m4.z = ((vmask >> (i + 2)) & 1ull) ? 1.0f : 0.0f;
            m4.w = ((vmask >> (i + 3)) & 1ull) ? 1.0f : 0.0f;
            w4.x = L[8 + i + 0] * inv;
            w4.y = L[8 + i + 1] * inv;
            w4.z = L[8 + i + 2] * inv;
            w4.w = L[8 + i + 3] * inv;
            *reinterpret_cast<float4*>(om + i) = m4;
            *reinterpret_cast<float4*>(ow + i) = w4;
        }
    }
}

extern "C" void kernel_launch(void* const* d_in, const int* in_sizes, int n_in,
                              void* d_out, int out_size) {
    const float* x   = (const float*)d_in[0];
    const float* ggw = (const float*)d_in[1];
    const float* egw = (const float*)d_in[2];
    float* out = (float*)d_out;

    const int tokens = in_sizes[0] / DIM;   // 16384
    const int grid = tokens / BM;           // 128
    router_kernel<<<grid, THREADS>>>(x, ggw, egw, out);
}

// round 3
// speedup vs baseline: 1.0142x; 1.0142x over previous
#include <cuda_runtime.h>

// HierarchicalRouter: two-level MoE router.
//   x               [16384, 2048] f32
//   group_gate_w    [8, 2048]     f32
//   expert_gate_w   [64, 2048]    f32
// out = concat(valid_mask[16384,64] as f32 0/1, normalized_weights[16384,64])
//
// R3: fused GEMM (M=16384, N=72, K=2048), fp32x2 FFMA packed over K
// (acc = (sum even k, sum odd k), summed at the end). 512 threads, 16 warps,
// thread tile 2 tokens x 9 experts. All smem accesses conflict-free or
// broadcast; no transpose, no weight duplication.

#define N_TOKENS 16384
#define DIM      2048
#define BM       128
#define BK       16
#define BKK      8              // k-pairs per tile
#define NITER    (DIM / BK)     // 128
#define THREADS  512
#define WEPAD    20             // floats per expert-group region per kk row
#define WROW2    (8 * WEPAD)    // 160
#define LSTRIDE  73

typedef unsigned long long u64;

__device__ __forceinline__ void ffma2(u64& acc, u64 a, u64 b) {
    asm("fma.rn.f32x2 %0, %1, %2, %0;" : "+l"(acc) : "l"(a), "l"(b));
}

struct SmemTiles {
    u64   xs[2][BKK][BM];     // (x[tok][2kk], x[tok][2kk+1]) per entry  16KB
    float ws[2][BKK][WROW2];  // per kk: 8 groups * (9 expert k-pairs)   10KB
};

__global__ __launch_bounds__(THREADS, 1)
void router_kernel(const float* __restrict__ x,
                   const float* __restrict__ ggw,
                   const float* __restrict__ egw,
                   float* __restrict__ out)
{
    __shared__ union {
        SmemTiles t;
        float logits[BM * LSTRIDE];  // reused after mainloop (37KB)
    } sm;

    const int tid   = threadIdx.x;
    const int wid   = tid >> 5;
    const int tg    = tid & 31;
    const int egp   = wid & 7;        // expert group 0..7
    const int thalf = wid >> 3;       // token half 0..1
    const int e0    = egp * 9;
    const int tok0  = blockIdx.x * BM;
    const int ta    = thalf * 64 + tg;   // token A (local)
    const int tb    = ta + 32;           // token B (local)

    // ---- x loader: thread covers token (tid&127), k-quad (tid>>7) ----
    const int ltok = tid & 127;
    const int xq   = tid >> 7;        // 0..3 -> k offset xq*4
    const float* xrow = x + (size_t)(tok0 + ltok) * DIM + xq * 4;

    // ---- w loader: threads 0..287, e = tid>>2, q = tid&3 ----
    const int we = tid >> 2;
    const int wq = tid & 3;
    const bool wload = (tid < 288);
    const float* wrow = nullptr;
    int wdst = 0;
    if (wload) {
        wrow = (we < 8) ? (ggw + (size_t)we * DIM)
                        : (egw + (size_t)(we - 8) * DIM);
        wrow += wq * 4;
        wdst = (we / 9) * WEPAD + (we % 9) * 2;
    }

    u64 acc[2][9];
#pragma unroll
    for (int p = 0; p < 2; p++)
#pragma unroll
        for (int j = 0; j < 9; j++) acc[p][j] = 0ull;

    float4 xa, wa;

    auto ldg_tile = [&](int it) {
        const int k0 = it * BK;
        xa = *reinterpret_cast<const float4*>(xrow + k0);
        if (wload)
            wa = *reinterpret_cast<const float4*>(wrow + k0);
    };

    auto sts_tile = [&](int b) {
        // x: float4 of 4 consecutive k = 2 k-pairs for this token
        *reinterpret_cast<float2*>(&sm.t.xs[b][xq * 2 + 0][ltok]) =
            make_float2(xa.x, xa.y);
        *reinterpret_cast<float2*>(&sm.t.xs[b][xq * 2 + 1][ltok]) =
            make_float2(xa.z, xa.w);
        // w: same, into the expert-group-packed rows
        if (wload) {
            *reinterpret_cast<float2*>(&sm.t.ws[b][wq * 2 + 0][wdst]) =
                make_float2(wa.x, wa.y);
            *reinterpret_cast<float2*>(&sm.t.ws[b][wq * 2 + 1][wdst]) =
                make_float2(wa.z, wa.w);
        }
    };

    auto compute = [&](int b) {
#pragma unroll
        for (int kk = 0; kk < BKK; kk++) {
            u64 xpa = sm.t.xs[b][kk][ta];        // LDS.64, conflict-free
            u64 xpb = sm.t.xs[b][kk][tb];
            const float* wr = &sm.t.ws[b][kk][egp * WEPAD];  // broadcast
            ulonglong2 w01 = *reinterpret_cast<const ulonglong2*>(wr + 0);
            ulonglong2 w23 = *reinterpret_cast<const ulonglong2*>(wr + 4);
            ulonglong2 w45 = *reinterpret_cast<const ulonglong2*>(wr + 8);
            ulonglong2 w67 = *reinterpret_cast<const ulonglong2*>(wr + 12);
            u64 w8 = *reinterpret_cast<const u64*>(wr + 16);

            ffma2(acc[0][0], xpa, w01.x); ffma2(acc[1][0], xpb, w01.x);
            ffma2(acc[0][1], xpa, w01.y); ffma2(acc[1][1], xpb, w01.y);
            ffma2(acc[0][2], xpa, w23.x); ffma2(acc[1][2], xpb, w23.x);
            ffma2(acc[0][3], xpa, w23.y); ffma2(acc[1][3], xpb, w23.y);
            ffma2(acc[0][4], xpa, w45.x); ffma2(acc[1][4], xpb, w45.x);
            ffma2(acc[0][5], xpa, w45.y); ffma2(acc[1][5], xpb, w45.y);
            ffma2(acc[0][6], xpa, w67.x); ffma2(acc[1][6], xpb, w67.x);
            ffma2(acc[0][7], xpa, w67.y); ffma2(acc[1][7], xpb, w67.y);
            ffma2(acc[0][8], xpa, w8);    ffma2(acc[1][8], xpb, w8);
        }
    };

    // ---- mainloop: double-buffered ----
    ldg_tile(0);
    sts_tile(0);
    __syncthreads();
    int cur = 0;
    for (int it = 0; it < NITER; ++it) {
        if (it + 1 < NITER) ldg_tile(it + 1);
        compute(cur);
        if (it + 1 < NITER) sts_tile(cur ^ 1);
        __syncthreads();
        cur ^= 1;
    }

    // ---- stage logits (even-k + odd-k halves summed) ----
#pragma unroll
    for (int j = 0; j < 9; j++) {
        float2 pa = *reinterpret_cast<float2*>(&acc[0][j]);
        float2 pb = *reinterpret_cast<float2*>(&acc[1][j]);
        sm.logits[ta * LSTRIDE + e0 + j] = pa.x + pa.y;
        sm.logits[tb * LSTRIDE + e0 + j] = pb.x + pb.y;
    }
    __syncthreads();

    // ---- epilogue: one thread per token ----
    if (tid < BM) {
        float* L = &sm.logits[tid * LSTRIDE];  // [0..7] group, [8..71] expert

        // group softmax
        float gl[8];
#pragma unroll
        for (int g = 0; g < 8; g++) gl[g] = L[g];
        float gmax = gl[0];
#pragma unroll
        for (int g = 1; g < 8; g++) gmax = fmaxf(gmax, gl[g]);
        float ge[8], gsum = 0.0f;
#pragma unroll
        for (int g = 0; g < 8; g++) { ge[g] = expf(gl[g] - gmax); gsum += ge[g]; }
        float gp[8];
#pragma unroll
        for (int g = 0; g < 8; g++) gp[g] = ge[g] / gsum;

        unsigned long long vmask = 0ull;
        float swsum = 0.0f;
#pragma unroll
        for (int g = 0; g < 8; g++) {
            const bool gm = (gp[g] >= 0.125f);
            float el[8];
#pragma unroll
            for (int e = 0; e < 8; e++) el[e] = L[8 + g * 8 + e];
            float emax = el[0];
#pragma unroll
            for (int e = 1; e < 8; e++) emax = fmaxf(emax, el[e]);
            float ee[8], esum = 0.0f;
#pragma unroll
            for (int e = 0; e < 8; e++) { ee[e] = expf(el[e] - emax); esum += ee[e]; }
#pragma unroll
            for (int e = 0; e < 8; e++) {
                const float ep = ee[e] / esum;
                const bool val = gm && (ep >= 0.125f);
                const float sw = val ? gp[g] * ep : 0.0f;
                swsum += sw;
                L[8 + g * 8 + e] = sw;
                if (val) vmask |= (1ull << (g * 8 + e));
            }
        }
        swsum = fmaxf(swsum, 1e-9f);
        const float inv = 1.0f / swsum;

        const int gt = tok0 + tid;
        float* om = out + (size_t)gt * 64;
        float* ow = out + (size_t)N_TOKENS * 64 + (size_t)gt * 64;
#pragma unroll
        for (int i = 0; i < 64; i += 4) {
            float4 m4, w4;
            m4.x = ((vmask >> (i + 0)) & 1ull) ? 1.0f : 0.0f;
            m4.y = ((vmask >> (i + 1)) & 1ull) ? 1.0f : 0.0f;
            m4.z = ((vmask >> (i + 2)) & 1ull) ? 1.0f : 0.0f;
            m4.w = ((vmask >> (i + 3)) & 1ull) ? 1.0f : 0.0f;
            w4.x = L[8 + i + 0] * inv;
            w4.y = L[8 + i + 1] * inv;
            w4.z = L[8 + i + 2] * inv;
            w4.w = L[8 + i + 3] * inv;
            *reinterpret_cast<float4*>(om + i) = m4;
            *reinterpret_cast<float4*>(ow + i) = w4;
        }
    }
}

extern "C" void kernel_launch(void* const* d_in, const int* in_sizes, int n_in,
                              void* d_out, int out_size) {
    const float* x   = (const float*)d_in[0];
    const float* ggw = (const float*)d_in[1];
    const float* egw = (const float*)d_in[2];
    float* out = (float*)d_out;

    const int tokens = in_sizes[0] / DIM;   // 16384
    const int grid = tokens / BM;           // 128
    router_kernel<<<grid, THREADS>>>(x, ggw, egw, out);
}